// round 1
// baseline (speedup 1.0000x reference)
#include <cuda_runtime.h>
#include <cuda_bf16.h>
#include <cstdint>

// ResiduePooling: scatter_mean(atom_features[2e6,128], residue_index(sorted) -> [250000,128])
//
// Pass 0: detect index dtype (int64 vs int32) -> device flag (deterministic).
// Pass 1: build segment start offsets from the sorted index (seg_start[r] = first
//         atom of residue r; seg_start[R] = n). Handles empty residues by filling
//         the gap range from the boundary-detecting thread.
// Pass 2: one warp per residue; each lane owns one float4 (4 of 128 features),
//         streams the residue's atom rows with coalesced 512B LDG.128 bursts,
//         scales by 1/count (0 if empty -> matches max(count,1) since sum==0),
//         writes one coalesced 512B row.

#define NUM_RESIDUES 250000
#define FEAT_DIM 128

__device__ int g_seg_start[NUM_RESIDUES + 1];
__device__ int g_idx_is64;

__global__ void detect_idx_dtype_kernel(const void* idx, int n) {
    // Safe region: first n int32 slots exist for both dtypes
    // (int32 buffer: n slots; int64 buffer: 2n slots).
    const int* v = (const int*)idx;
    // int64 little-endian, values in [0, 250000): every odd int32 slot is the
    // zero high word. Genuine int32 sorted data has v[odd pos near end] ~ pos/8.
    int probe = (v[1] | v[1001] | v[100001] | v[n - 1]);
    g_idx_is64 = (probe == 0) ? 1 : 0;
}

__global__ void build_offsets_kernel(const void* idxv, int n) {
    const bool is64 = (g_idx_is64 != 0);
    const long long* i64 = (const long long*)idxv;
    const int* i32 = (const int*)idxv;

    int i = blockIdx.x * blockDim.x + threadIdx.x;
    if (i >= n) return;

    int r    = is64 ? (int)i64[i] : i32[i];
    int prev = (i == 0) ? -1 : (is64 ? (int)i64[i - 1] : i32[i - 1]);

    // This thread owns residue boundaries in (prev, r].
    for (int q = prev + 1; q <= r; q++) g_seg_start[q] = i;

    if (i == n - 1) {
        for (int q = r + 1; q <= NUM_RESIDUES; q++) g_seg_start[q] = n;
    }
}

__global__ void __launch_bounds__(256) pool_kernel(const float* __restrict__ feat,
                                                   float* __restrict__ out) {
    int gwarp = (blockIdx.x * blockDim.x + threadIdx.x) >> 5;  // residue id
    int lane  = threadIdx.x & 31;
    if (gwarp >= NUM_RESIDUES) return;

    int s = g_seg_start[gwarp];
    int e = g_seg_start[gwarp + 1];

    float4 acc = make_float4(0.f, 0.f, 0.f, 0.f);

    const float4* frow = (const float4*)(feat + (size_t)s * FEAT_DIM);
    int cnt = e - s;

    // Unroll by 2 for MLP (two independent 512B row reads in flight per warp).
    int a = 0;
    for (; a + 2 <= cnt; a += 2) {
        float4 v0 = frow[(size_t)a * 32 + lane];
        float4 v1 = frow[(size_t)(a + 1) * 32 + lane];
        acc.x += v0.x; acc.y += v0.y; acc.z += v0.z; acc.w += v0.w;
        acc.x += v1.x; acc.y += v1.y; acc.z += v1.z; acc.w += v1.w;
    }
    if (a < cnt) {
        float4 v0 = frow[(size_t)a * 32 + lane];
        acc.x += v0.x; acc.y += v0.y; acc.z += v0.z; acc.w += v0.w;
    }

    float inv = (cnt > 0) ? (1.0f / (float)cnt) : 0.0f;  // empty: sum==0 -> 0 (== sum/max(cnt,1))
    acc.x *= inv; acc.y *= inv; acc.z *= inv; acc.w *= inv;

    ((float4*)(out + (size_t)gwarp * FEAT_DIM))[lane] = acc;
}

extern "C" void kernel_launch(void* const* d_in, const int* in_sizes, int n_in,
                              void* d_out, int out_size) {
    const float* feat = (const float*)d_in[0];
    const void* idx   = (const void*)d_in[1];
    int n_atoms       = in_sizes[1];

    detect_idx_dtype_kernel<<<1, 1>>>(idx, n_atoms);

    int threads = 256;
    int blocks = (n_atoms + threads - 1) / threads;
    build_offsets_kernel<<<blocks, threads>>>(idx, n_atoms);

    // 8 warps per block -> 8 residues per block
    int res_per_block = 8;
    int pool_blocks = (NUM_RESIDUES + res_per_block - 1) / res_per_block;
    pool_kernel<<<pool_blocks, 256>>>(feat, (float*)d_out);
}

// round 2
// speedup vs baseline: 1.0066x; 1.0066x over previous
#include <cuda_runtime.h>
#include <cuda_bf16.h>
#include <cstdint>

// ResiduePooling: scatter_mean(atom_features[2e6,128], residue_index(sorted) -> [250000,128])
//
// Pass 1: build segment start offsets from the sorted index. Index dtype
//         (int64 vs int32) detected inline per-thread from uniform probe loads
//         (little-endian int64 values < 2^31 have zero odd int32 slots).
// Pass 2: one warp per residue; each lane owns one float4 (4 of 128 features),
//         streams the residue's atom rows with coalesced 512B LDG.128 bursts
//         (evict-streaming hints: zero reuse), scales by 1/count, writes one
//         coalesced 512B row. Empty residues write 0 (== 0/max(cnt,1)).

#define NUM_RESIDUES 250000
#define FEAT_DIM 128

__device__ int g_seg_start[NUM_RESIDUES + 1];

__device__ __forceinline__ bool detect_is64(const int* v, int n) {
    // Safe region: first n int32 slots exist for both dtypes.
    int p0 = __ldg(v + 1);
    int p1 = __ldg(v + ((n > 1002) ? 1001 : 1));
    int p2 = __ldg(v + ((n > 100002) ? 100001 : 1));
    int p3 = __ldg(v + (n - 1));
    return ((p0 | p1 | p2 | p3) == 0);
}

__global__ void __launch_bounds__(256) build_offsets_kernel(const void* idxv, int n) {
    const bool is64 = detect_is64((const int*)idxv, n);
    const long long* i64 = (const long long*)idxv;
    const int* i32 = (const int*)idxv;

    int i = blockIdx.x * blockDim.x + threadIdx.x;
    if (i >= n) return;

    int r    = is64 ? (int)i64[i] : i32[i];
    int prev = (i == 0) ? -1 : (is64 ? (int)i64[i - 1] : i32[i - 1]);

    // This thread owns residue boundaries in (prev, r].
    for (int q = prev + 1; q <= r; q++) g_seg_start[q] = i;

    if (i == n - 1) {
        for (int q = r + 1; q <= NUM_RESIDUES; q++) g_seg_start[q] = n;
    }
}

__global__ void __launch_bounds__(256) pool_kernel(const float* __restrict__ feat,
                                                   float* __restrict__ out) {
    int gwarp = (blockIdx.x * blockDim.x + threadIdx.x) >> 5;  // residue id
    int lane  = threadIdx.x & 31;
    if (gwarp >= NUM_RESIDUES) return;

    int s = __ldg(&g_seg_start[gwarp]);
    int e = __ldg(&g_seg_start[gwarp + 1]);
    int cnt = e - s;

    const float4* frow = (const float4*)(feat + (size_t)s * FEAT_DIM);

    float4 acc0 = make_float4(0.f, 0.f, 0.f, 0.f);
    float4 acc1 = make_float4(0.f, 0.f, 0.f, 0.f);

    // Unroll by 4: four independent 512B row reads in flight per warp.
    int a = 0;
    for (; a + 4 <= cnt; a += 4) {
        float4 v0 = __ldcs(&frow[(size_t)(a + 0) * 32 + lane]);
        float4 v1 = __ldcs(&frow[(size_t)(a + 1) * 32 + lane]);
        float4 v2 = __ldcs(&frow[(size_t)(a + 2) * 32 + lane]);
        float4 v3 = __ldcs(&frow[(size_t)(a + 3) * 32 + lane]);
        acc0.x += v0.x; acc0.y += v0.y; acc0.z += v0.z; acc0.w += v0.w;
        acc1.x += v1.x; acc1.y += v1.y; acc1.z += v1.z; acc1.w += v1.w;
        acc0.x += v2.x; acc0.y += v2.y; acc0.z += v2.z; acc0.w += v2.w;
        acc1.x += v3.x; acc1.y += v3.y; acc1.z += v3.z; acc1.w += v3.w;
    }
    if (a + 2 <= cnt) {
        float4 v0 = __ldcs(&frow[(size_t)(a + 0) * 32 + lane]);
        float4 v1 = __ldcs(&frow[(size_t)(a + 1) * 32 + lane]);
        acc0.x += v0.x; acc0.y += v0.y; acc0.z += v0.z; acc0.w += v0.w;
        acc1.x += v1.x; acc1.y += v1.y; acc1.z += v1.z; acc1.w += v1.w;
        a += 2;
    }
    if (a < cnt) {
        float4 v0 = __ldcs(&frow[(size_t)a * 32 + lane]);
        acc0.x += v0.x; acc0.y += v0.y; acc0.z += v0.z; acc0.w += v0.w;
    }

    float inv = (cnt > 0) ? (1.0f / (float)cnt) : 0.0f;
    float4 r;
    r.x = (acc0.x + acc1.x) * inv;
    r.y = (acc0.y + acc1.y) * inv;
    r.z = (acc0.z + acc1.z) * inv;
    r.w = (acc0.w + acc1.w) * inv;

    __stcs((float4*)(out + (size_t)gwarp * FEAT_DIM) + lane, r);
}

extern "C" void kernel_launch(void* const* d_in, const int* in_sizes, int n_in,
                              void* d_out, int out_size) {
    const float* feat = (const float*)d_in[0];
    const void* idx   = (const void*)d_in[1];
    int n_atoms       = in_sizes[1];

    int threads = 256;
    int blocks = (n_atoms + threads - 1) / threads;
    build_offsets_kernel<<<blocks, threads>>>(idx, n_atoms);

    // 8 warps per block -> 8 residues per block
    int res_per_block = 8;
    int pool_blocks = (NUM_RESIDUES + res_per_block - 1) / res_per_block;
    pool_kernel<<<pool_blocks, 256>>>(feat, (float*)d_out);
}

// round 4
// speedup vs baseline: 1.0229x; 1.0162x over previous
#include <cuda_runtime.h>
#include <cuda_bf16.h>
#include <cstdint>

// ResiduePooling: scatter_mean(atom_features[2e6,128], residue_index(sorted) -> [250000,128])
//
// Pass 1: build segment start offsets from the sorted index (vectorized: one
//         thread per 4 indices, wide loads). Index dtype (int64 vs int32)
//         detected inline from uniform probe loads.
// Pass 2: one warp per residue, 64-thread blocks (2 warps) to minimize
//         intra-block tail skew from variable segment lengths. Each lane owns
//         one float4 of the 128-wide feature row; streams the segment with
//         coalesced 512B LDG.128 bursts (evict-streaming), scales by 1/count,
//         writes one coalesced 512B row. Empty residues write 0.

#define NUM_RESIDUES 250000
#define FEAT_DIM 128

__device__ int g_seg_start[NUM_RESIDUES + 1];

__device__ __forceinline__ bool detect_is64(const int* __restrict__ v, int n) {
    // Safe region: first n int32 slots exist for both dtypes.
    // int64 little-endian values < 2^31: every odd int32 slot is zero.
    int p0 = __ldg(v + 1);
    int p1 = __ldg(v + ((n > 1002) ? 1001 : 1));
    int p2 = __ldg(v + ((n > 100002) ? 100001 : 1));
    int p3 = __ldg(v + (n - 1));
    return ((p0 | p1 | p2 | p3) == 0);
}

__global__ void __launch_bounds__(256) build_offsets_kernel(const void* __restrict__ idxv, int n) {
    const bool is64 = detect_is64((const int*)idxv, n);

    int t = blockIdx.x * blockDim.x + threadIdx.x;
    int base = t * 4;
    if (base >= n) return;

    int r[4];
    int nvalid = (n - base >= 4) ? 4 : (n - base);

    if (is64) {
        const long long* __restrict__ p = (const long long*)idxv;
        if (nvalid == 4) {
            // Two 16B loads (no 32B __ldg overload for longlong4).
            ulonglong2 v0 = *(const ulonglong2*)(p + base);
            ulonglong2 v1 = *(const ulonglong2*)(p + base + 2);
            r[0] = (int)v0.x; r[1] = (int)v0.y; r[2] = (int)v1.x; r[3] = (int)v1.y;
        } else {
            for (int j = 0; j < nvalid; j++) r[j] = (int)p[base + j];
        }
    } else {
        const int* __restrict__ p = (const int*)idxv;
        if (nvalid == 4) {
            int4 v = *(const int4*)(p + base);
            r[0] = v.x; r[1] = v.y; r[2] = v.z; r[3] = v.w;
        } else {
            for (int j = 0; j < nvalid; j++) r[j] = p[base + j];
        }
    }

    int prev;
    if (base == 0) {
        prev = -1;
    } else {
        prev = is64 ? (int)((const long long*)idxv)[base - 1]
                    : ((const int*)idxv)[base - 1];
    }

    #pragma unroll
    for (int j = 0; j < 4; j++) {
        if (j < nvalid) {
            int rj = r[j];
            for (int q = prev + 1; q <= rj; q++) g_seg_start[q] = base + j;
            prev = rj;
        }
    }

    if (base + nvalid == n) {
        for (int q = prev + 1; q <= NUM_RESIDUES; q++) g_seg_start[q] = n;
    }
}

__global__ void __launch_bounds__(64) pool_kernel(const float* __restrict__ feat,
                                                  float* __restrict__ out) {
    int gwarp = (blockIdx.x * blockDim.x + threadIdx.x) >> 5;  // residue id
    int lane  = threadIdx.x & 31;
    if (gwarp >= NUM_RESIDUES) return;

    int s = __ldg(&g_seg_start[gwarp]);
    int e = __ldg(&g_seg_start[gwarp + 1]);
    int cnt = e - s;

    // Per-row stride in float4 units = 128/4 = 32.
    const float4* __restrict__ p = (const float4*)(feat + (size_t)s * FEAT_DIM) + lane;

    float4 acc0 = make_float4(0.f, 0.f, 0.f, 0.f);
    float4 acc1 = make_float4(0.f, 0.f, 0.f, 0.f);

    int a = 0;
    // Unroll by 4: four independent 512B row reads in flight per warp.
    for (; a + 4 <= cnt; a += 4) {
        float4 v0 = __ldcs(p);
        float4 v1 = __ldcs(p + 32);
        float4 v2 = __ldcs(p + 64);
        float4 v3 = __ldcs(p + 96);
        p += 128;
        acc0.x += v0.x; acc0.y += v0.y; acc0.z += v0.z; acc0.w += v0.w;
        acc1.x += v1.x; acc1.y += v1.y; acc1.z += v1.z; acc1.w += v1.w;
        acc0.x += v2.x; acc0.y += v2.y; acc0.z += v2.z; acc0.w += v2.w;
        acc1.x += v3.x; acc1.y += v3.y; acc1.z += v3.z; acc1.w += v3.w;
    }
    if (a + 2 <= cnt) {
        float4 v0 = __ldcs(p);
        float4 v1 = __ldcs(p + 32);
        p += 64;
        a += 2;
        acc0.x += v0.x; acc0.y += v0.y; acc0.z += v0.z; acc0.w += v0.w;
        acc1.x += v1.x; acc1.y += v1.y; acc1.z += v1.z; acc1.w += v1.w;
    }
    if (a < cnt) {
        float4 v0 = __ldcs(p);
        acc0.x += v0.x; acc0.y += v0.y; acc0.z += v0.z; acc0.w += v0.w;
    }

    float inv = (cnt > 0) ? (1.0f / (float)cnt) : 0.0f;
    float4 r;
    r.x = (acc0.x + acc1.x) * inv;
    r.y = (acc0.y + acc1.y) * inv;
    r.z = (acc0.z + acc1.z) * inv;
    r.w = (acc0.w + acc1.w) * inv;

    __stcs((float4*)(out + (size_t)gwarp * FEAT_DIM) + lane, r);
}

extern "C" void kernel_launch(void* const* d_in, const int* in_sizes, int n_in,
                              void* d_out, int out_size) {
    const float* feat = (const float*)d_in[0];
    const void* idx   = (const void*)d_in[1];
    int n_atoms       = in_sizes[1];

    int elems_per_thread = 4;
    int threads = 256;
    int work = (n_atoms + elems_per_thread - 1) / elems_per_thread;
    int blocks = (work + threads - 1) / threads;
    build_offsets_kernel<<<blocks, threads>>>(idx, n_atoms);

    // 2 warps per block -> 2 residues per block (minimize tail skew)
    int res_per_block = 2;
    int pool_blocks = (NUM_RESIDUES + res_per_block - 1) / res_per_block;
    pool_kernel<<<pool_blocks, 64>>>(feat, (float*)d_out);
}